// round 11
// baseline (speedup 1.0000x reference)
#include <cuda_runtime.h>
#include <cuda_bf16.h>
#include <math.h>

#define NB    8
#define NSEQ  1024
#define NDIM  64
#define NPAIR 5
#define NPB   40               // pair*8 + batch
#define NDIAG 2047
#define NTILES 1888            // 16 pbs * 64 tiles + 24 sym pbs * 36 tiles
#define DSTRIDE ((size_t)2048 * 1024)   // padded: diag 2047 is permanent zeros

// tensor order matches d_in: 0=TGT, 1=OTH, 2=X
__constant__ int c_pa[NPAIR] = {2, 0, 0, 1, 1};  // first arg (rows i)
__constant__ int c_pb[NPAIR] = {2, 2, 0, 2, 1};  // second arg (rows j)

__device__ __nv_bfloat16 g_hi[3 * NB * NSEQ * NDIM];      // bf16(x)
__device__ __nv_bfloat16 g_lo[3 * NB * NSEQ * NDIM];      // bf16(x - hi)
__device__ float g_w[NPB * 2048 * 1024];                  // exp(dot-1), diag-major; invalid = 0
__device__ float g_sdtw[NPB];
__device__ int   g_ticket;                                // producer work queue
__device__ int   g_done[NPB * 16];                        // per-(pb, wave) tile completions

// per-wave tile counts
__device__ __forceinline__ int cnt_ns(int s)  { return 8 - abs(s - 7); }
__device__ __forceinline__ int cnt_sym(int s) { return (s >> 1) - max(0, s - 7) + 1; }

__device__ __forceinline__ int ld_acq(const int* p) {
    int v;
    asm volatile("ld.acquire.gpu.b32 %0, [%1];" : "=r"(v) : "l"(p));
    return v;
}

// ---------------------------------------------------------------------------
// Kernel 1: row-normalize + bf16 hi/lo split. One warp per row.
// Block 0 also resets the producer/consumer bookkeeping for this replay.
// ---------------------------------------------------------------------------
__global__ void norm_kernel(const float* __restrict__ TGT,
                            const float* __restrict__ OTH,
                            const float* __restrict__ X) {
    if (blockIdx.x == 0) {
        if (threadIdx.x == 0) g_ticket = 0;
        for (int i = threadIdx.x; i < NPB * 16; i += 256) g_done[i] = 0;
    }
    int row  = blockIdx.x * 8 + (threadIdx.x >> 5);   // 0 .. 24575
    int lane = threadIdx.x & 31;
    const float* src = (row < 8192) ? TGT : (row < 16384 ? OTH : X);
    int lrow = row & 8191;
    float2 v = reinterpret_cast<const float2*>(src + (size_t)lrow * NDIM)[lane];
    float s = v.x * v.x + v.y * v.y;
    #pragma unroll
    for (int o = 16; o; o >>= 1) s += __shfl_xor_sync(0xffffffffu, s, o);
    float scale = (s > 1e-16f) ? rsqrtf(s) : 1e8f;
    float nx = v.x * scale, ny = v.y * scale;
    __nv_bfloat16 hx = __float2bfloat16(nx);
    __nv_bfloat16 hy = __float2bfloat16(ny);
    __nv_bfloat16 lx = __float2bfloat16(nx - __bfloat162float(hx));
    __nv_bfloat16 ly = __float2bfloat16(ny - __bfloat162float(hy));
    __nv_bfloat162 hp; hp.x = hx; hp.y = hy;
    __nv_bfloat162 lp; lp.x = lx; lp.y = ly;
    reinterpret_cast<__nv_bfloat162*>(g_hi + (size_t)row * NDIM)[lane] = hp;
    reinterpret_cast<__nv_bfloat162*>(g_lo + (size_t)row * NDIM)[lane] = lp;
}

// ---------------------------------------------------------------------------
// Kernel 2 (FUSED): persistent producer/consumer.
//  CTAs 0..39   : skewed-warp soft-DTW DP (1 barrier per 32 diagonals).
//  CTAs 40..255 : GEMM producers off a global ticket ordered by wave s=ti+tj.
// ---------------------------------------------------------------------------
#define MMA_BF16(ACC, A0, A1, A2, A3, B0, B1)                                   \
    asm volatile(                                                               \
        "mma.sync.aligned.m16n8k16.row.col.f32.bf16.bf16.f32 "                  \
        "{%0,%1,%2,%3}, {%4,%5,%6,%7}, {%8,%9}, {%0,%1,%2,%3};"                 \
        : "+f"((ACC)[0]), "+f"((ACC)[1]), "+f"((ACC)[2]), "+f"((ACC)[3])        \
        : "r"(A0), "r"(A1), "r"(A2), "r"(A3), "r"(B0), "r"(B1))

#define HPITCH 40   // halves per row (32 + 8 pad): word stride 20 -> conflict-free

__global__ void __launch_bounds__(256, 2) fused_kernel() {
    __shared__ __align__(16) __nv_bfloat16 smbuf[4 * 128 * HPITCH];  // 40 KB (producer)
    __shared__ float bbuf[2][8][32];   // DP: per-warp boundary E1, parity ring
    __shared__ float Lpub[2][8];       // DP: per-warp log-offset at interval start
    __shared__ int   sticket;          // producer ticket broadcast

    if (blockIdx.x < NPB) {
        // =================== CONSUMER: skewed-warp soft-DTW DP ===================
        const int pb   = blockIdx.x;
        const int pair = pb >> 3;
        const bool symp = (c_pa[pair] == c_pb[pair]);
        const int tid  = threadIdx.x;
        const int lane = tid & 31;
        const int w    = tid >> 5;
        const int wm1  = (w == 0) ? 0 : w - 1;

        // lane's float4 = rows [128w + 4*lane .. +3]; diag d at base[d*256]
        const float4* base =
            reinterpret_cast<const float4*>(g_w + (size_t)pb * DSTRIDE) + 32 * w + lane;

        float E1[4]  = {0.f, 0.f, 0.f, 0.f};
        float E2s[4] = {0.f, 0.f, 0.f, 0.f};
        if (tid == 0) E2s[0] = 1.0f;       // virtual corner exp(-R[-1,-1]) = 1
        float L = 0.f;                      // stored = E_true * exp(L)
        float carry = 0.f;                  // neighbor boundary at own-block diag -1, own scale
        int s_checked = 0;                  // used by thread 0 only

        for (int m = 0; m < 71; m++) {
            if (tid == 0) {
                int dmax   = 32 * min(m, 63) + 31;
                int s_need = min(14, dmax >> 7);
                while (s_checked <= s_need) {
                    int need = symp ? cnt_sym(s_checked) : cnt_ns(s_checked);
                    if (ld_acq(&g_done[pb * 16 + s_checked]) >= need) s_checked++;
                    else __nanosleep(128);
                }
            }
            __syncthreads();                // interval barrier (the ONLY one per 32 steps)

            const int b = m - w;            // this warp's diag block
            if (b >= 0 && b < 64) {
                const bool last = (b == 63);        // block 63 = diags 2016..2046 (31 steps)
                const float* nbuf = bbuf[(m + 1) & 1][wm1];   // neighbor's previous interval
                const float Lnb = (w == 0) ? 0.f : Lpub[(m + 1) & 1][wm1];
                float f = (w == 0) ? 0.f : __expf(L - Lnb);
                if (lane == 0) Lpub[m & 1][w] = L;

                const size_t d0 = (size_t)(b * 32) * 256;
                float4 rbuf[4];
                #pragma unroll
                for (int q = 0; q < 4; q++) rbuf[q] = base[d0 + (size_t)q * 256];

                #pragma unroll
                for (int jq = 0; jq < 8; jq++) {
                    #pragma unroll
                    for (int jj = 0; jj < 4; jj++) {
                        const int j = jq * 4 + jj;
                        float4 wv = rbuf[jj];
                        if (j + 4 < 32) rbuf[jj] = base[d0 + (size_t)(j + 4) * 256];
                        if (j == 31 && last) continue;   // diag 2047 doesn't exist
                        float nb = __shfl_up_sync(0xffffffffu, E1[3], 1);
                        if (lane == 0) nb = (j == 0) ? carry : f * nbuf[j - 1];
                        float sh0 = nb, sh1 = E1[0], sh2 = E1[1], sh3 = E1[2];
                        float n0 = wv.x * ((E1[0] + sh0) + E2s[0]);
                        float n1 = wv.y * ((E1[1] + sh1) + E2s[1]);
                        float n2 = wv.z * ((E1[2] + sh2) + E2s[2]);
                        float n3 = wv.w * ((E1[3] + sh3) + E2s[3]);
                        E2s[0] = sh0; E2s[1] = sh1; E2s[2] = sh2; E2s[3] = sh3;
                        E1[0] = n0; E1[1] = n1; E1[2] = n2; E1[3] = n3;
                        if (lane == 31) bbuf[m & 1][w][j] = n3;
                    }
                }

                if (last) {
                    if (w == 7 && lane == 31) g_sdtw[pb] = L - __logf(E1[3]);
                } else {
                    carry = f * nbuf[31];   // neighbor diag (32b+31) = own next-block k-1 seed
                    // per-warp rescale
                    float mx = fmaxf(fmaxf(fmaxf(E1[0], E1[1]), fmaxf(E1[2], E1[3])),
                                     fmaxf(fmaxf(E2s[0], E2s[1]), fmaxf(E2s[2], E2s[3])));
                    mx = fmaxf(mx, carry);
                    #pragma unroll
                    for (int o = 16; o; o >>= 1)
                        mx = fmaxf(mx, __shfl_xor_sync(0xffffffffu, mx, o));
                    if (mx > 1e-30f) {
                        float sc = 1.0f / mx;
                        L -= __logf(mx);
                        E1[0] *= sc; E1[1] *= sc; E1[2] *= sc; E1[3] *= sc;
                        E2s[0] *= sc; E2s[1] *= sc; E2s[2] *= sc; E2s[3] *= sc;
                        carry *= sc;
                    } else if (w > 0) {
                        // dormant band: state is (essentially) all zero. Adopt the
                        // neighbor's scale so L never drifts far from L_nb; otherwise
                        // f = exp(L - L_nb) underflows when this band goes active.
                        E1[0] = E1[1] = E1[2] = E1[3] = 0.f;
                        E2s[0] = E2s[1] = E2s[2] = E2s[3] = 0.f;
                        carry = 0.f;
                        L = Lnb;
                    }
                }
            }
        }
        return;
    }

    // =================== PRODUCER: cost tiles ===================
    __nv_bfloat16* Ah = smbuf;
    __nv_bfloat16* Al = smbuf + 128 * HPITCH;
    __nv_bfloat16* Bh = smbuf + 2 * 128 * HPITCH;
    __nv_bfloat16* Bl = smbuf + 3 * 128 * HPITCH;

    const int t    = threadIdx.x;
    const int w    = t >> 5;
    const int lane = t & 31;
    const int lq   = lane >> 2;
    const int lr   = lane & 3;
    const int m0   = w * 16;

    for (;;) {
        if (t == 0) sticket = atomicAdd(&g_ticket, 1);
        __syncthreads();
        const int ticket = sticket;
        if (ticket >= NTILES) return;

        // decode ticket -> (s, pb, ti, tj); tiles ordered by wave s
        int s = 0, acc0 = 0;
        for (;; s++) {
            int wsz = 24 * cnt_sym(s) + 16 * cnt_ns(s);
            if (ticket < acc0 + wsz) break;
            acc0 += wsz;
        }
        int r  = ticket - acc0;
        int cs = cnt_sym(s), cn = cnt_ns(s), lo = max(0, s - 7);
        int pb, ti;
        if (r < 24 * cs) {
            int q = r / cs; ti = lo + (r % cs);
            pb = ((q >> 3) * 2) * 8 + (q & 7);          // pairs 0,2,4 (symmetric)
        } else {
            r -= 24 * cs;
            int q = r / cn; ti = lo + (r % cn);
            pb = ((q >> 3) * 2 + 1) * 8 + (q & 7);      // pairs 1,3
        }
        const int tj = s - ti;
        const int pair  = pb >> 3;
        const int batch = pb & 7;
        const bool mirror = (c_pa[pair] == c_pb[pair]) && (ti < tj);
        const int i0 = ti * 128, j0t = tj * 128;

        const size_t offA = ((size_t)(c_pa[pair] * NB + batch)) * NSEQ * NDIM + (size_t)i0 * NDIM;
        const size_t offB = ((size_t)(c_pb[pair] * NB + batch)) * NSEQ * NDIM + (size_t)j0t * NDIM;
        const __nv_bfloat16* Aph = g_hi + offA; const __nv_bfloat16* Apl = g_lo + offA;
        const __nv_bfloat16* Bph = g_hi + offB; const __nv_bfloat16* Bpl = g_lo + offB;

        float acc[16][4];
        #pragma unroll
        for (int j = 0; j < 16; j++)
            #pragma unroll
            for (int c = 0; c < 4; c++) acc[j][c] = 0.f;

        for (int kc0 = 0; kc0 < NDIM; kc0 += 32) {
            __syncthreads();
            #pragma unroll
            for (int p = 0; p < 2; p++) {
                int f = t + p * 256;
                int row = f >> 2, q = f & 3;
                size_t go = (size_t)row * NDIM + kc0 + q * 8;
                int    so = row * HPITCH + q * 8;
                *reinterpret_cast<uint4*>(&Ah[so]) = *reinterpret_cast<const uint4*>(&Aph[go]);
                *reinterpret_cast<uint4*>(&Al[so]) = *reinterpret_cast<const uint4*>(&Apl[go]);
                *reinterpret_cast<uint4*>(&Bh[so]) = *reinterpret_cast<const uint4*>(&Bph[go]);
                *reinterpret_cast<uint4*>(&Bl[so]) = *reinterpret_cast<const uint4*>(&Bpl[go]);
            }
            __syncthreads();

            #pragma unroll
            for (int kk = 0; kk < 2; kk++) {
                const int k = kk * 16;
                unsigned ahi[4], alo[4];
                int ab  = (m0 + lq) * HPITCH + k + 2 * lr;
                int ab8 = (m0 + lq + 8) * HPITCH + k + 2 * lr;
                ahi[0] = *reinterpret_cast<unsigned*>(&Ah[ab]);
                ahi[1] = *reinterpret_cast<unsigned*>(&Ah[ab8]);
                ahi[2] = *reinterpret_cast<unsigned*>(&Ah[ab + 8]);
                ahi[3] = *reinterpret_cast<unsigned*>(&Ah[ab8 + 8]);
                alo[0] = *reinterpret_cast<unsigned*>(&Al[ab]);
                alo[1] = *reinterpret_cast<unsigned*>(&Al[ab8]);
                alo[2] = *reinterpret_cast<unsigned*>(&Al[ab + 8]);
                alo[3] = *reinterpret_cast<unsigned*>(&Al[ab8 + 8]);
                #pragma unroll
                for (int j = 0; j < 16; j++) {
                    int bo = (j * 8 + lq) * HPITCH + k + 2 * lr;
                    unsigned bhi0 = *reinterpret_cast<unsigned*>(&Bh[bo]);
                    unsigned bhi1 = *reinterpret_cast<unsigned*>(&Bh[bo + 8]);
                    unsigned blo0 = *reinterpret_cast<unsigned*>(&Bl[bo]);
                    unsigned blo1 = *reinterpret_cast<unsigned*>(&Bl[bo + 8]);
                    MMA_BF16(acc[j], ahi[0], ahi[1], ahi[2], ahi[3], bhi0, bhi1);
                    MMA_BF16(acc[j], ahi[0], ahi[1], ahi[2], ahi[3], blo0, blo1);
                    MMA_BF16(acc[j], alo[0], alo[1], alo[2], alo[3], bhi0, bhi1);
                }
            }
        }

        // epilogue: 4 chunks of 32 rows -> SMEM -> diag-major exp writes
        float* Cs = reinterpret_cast<float*>(smbuf);
        const size_t dbase = (size_t)pb * DSTRIDE;
        for (int c = 0; c < 4; c++) {
            __syncthreads();
            if ((w >> 1) == c) {
                int rbase = (w & 1) * 16 + lq;
                #pragma unroll
                for (int j = 0; j < 16; j++) {
                    int col = j * 8 + 2 * lr;
                    Cs[rbase * 136 + col]           = acc[j][0];
                    Cs[rbase * 136 + col + 1]       = acc[j][1];
                    Cs[(rbase + 8) * 136 + col]     = acc[j][2];
                    Cs[(rbase + 8) * 136 + col + 1] = acc[j][3];
                }
            }
            __syncthreads();
            int kb  = i0 + j0t + c * 32;
            int gi0 = i0 + c * 32;
            for (int kl = w; kl < 159; kl += 8) {
                int ri = lane;
                int jl = kl - ri;
                if (jl >= 0 && jl < 128) {
                    float val = __expf(Cs[ri * 136 + jl] - 1.0f);
                    size_t krow = dbase + (size_t)(kb + kl) * NSEQ;
                    g_w[krow + (gi0 + ri)] = val;
                    if (mirror) g_w[krow + (j0t + jl)] = val;
                }
            }
        }
        __syncthreads();
        if (t == 0) {
            __threadfence();                          // release tile writes
            atomicAdd(&g_done[pb * 16 + s], 1);
        }
    }
}

// ---------------------------------------------------------------------------
// Kernel 3: final MSE reduction
// ---------------------------------------------------------------------------
__global__ void final_kernel(const float* __restrict__ labels, float* __restrict__ out) {
    int b = threadIdx.x;
    float v = 0.f;
    if (b < NB) {
        float sXX = g_sdtw[0 * NB + b];
        float sTX = g_sdtw[1 * NB + b];
        float sTT = g_sdtw[2 * NB + b];
        float sOX = g_sdtw[3 * NB + b];
        float sOO = g_sdtw[4 * NB + b];
        float dt = sTX - 0.5f * (sTT + sXX);
        float dq = sOX - 0.5f * (sOO + sXX);
        float e  = dt - dq - labels[0];
        v = e * e;
    }
    #pragma unroll
    for (int o = 16; o; o >>= 1) v += __shfl_xor_sync(0xffffffffu, v, o);
    if (b == 0) out[0] = v * (1.0f / NB);
}

// ---------------------------------------------------------------------------
extern "C" void kernel_launch(void* const* d_in, const int* in_sizes, int n_in,
                              void* d_out, int out_size) {
    const float* TGT    = (const float*)d_in[0];
    const float* OTH    = (const float*)d_in[1];
    const float* X      = (const float*)d_in[2];
    const float* labels = (const float*)d_in[3];
    float* out = (float*)d_out;

    norm_kernel<<<3072, 256>>>(TGT, OTH, X);
    fused_kernel<<<256, 256>>>();
    final_kernel<<<1, 32>>>(labels, out);
}